// round 1
// baseline (speedup 1.0000x reference)
#include <cuda_runtime.h>

// Depthwise separable 4x4 blur, filter [1,3,3,1] (x) [1,3,3,1] / 64.
// Input  (8, 256, 64, 512) fp32, W-pad circular(1), H-pad reflect(1).
// Output (8, 256, 63, 511) fp32.
//
// Strategy: one thread per output column per image. Rolling horizontal-blur
// registers give 4 global loads per input row (coalesced; tap overlap served
// by L1), 63 coalesced stores. Pure HBM-streaming kernel.

#define W   512
#define H   64
#define OW  511
#define OH  63

__global__ __launch_bounds__(128) void Blur_49976239456711_kernel(
    const float* __restrict__ in, float* __restrict__ out)
{
    int ox  = blockIdx.x * blockDim.x + threadIdx.x;
    int img = blockIdx.y;
    if (ox >= OW) return;

    const float* __restrict__ src = in  + (size_t)img * (H * W);
    float*       __restrict__ dst = out + (size_t)img * (OH * OW) + ox;

    // padded col px = ox + j maps to src col (ox + j - 1) mod 512
    const int c0 = (ox + W - 1) & (W - 1);  // j=0
    const int c1 = ox;                      // j=1
    const int c2 = ox + 1;                  // j=2 (<= 511, no wrap)
    const int c3 = (ox + 2) & (W - 1);      // j=3 (512 wraps to 0)

    auto hblur = [&](int y) -> float {
        const float* r = src + y * W;
        float a = __ldg(r + c0);
        float b = __ldg(r + c1);
        float c = __ldg(r + c2);
        float d = __ldg(r + c3);
        return (a + d) + 3.0f * (b + c);
    };

    // Reflect pad rows: padded row py -> src row: py==0 -> 1, py==65 -> 62, else py-1.
    // HB[py] rolling window of 4.
    float hb0 = hblur(1);   // HB[0]
    float hb1 = hblur(0);   // HB[1]
    float hb2 = hb0;        // HB[2] == hblur(1)
    float hb3;

    #pragma unroll 4
    for (int oy = 0; oy < OH - 1; ++oy) {       // oy = 0..61: HB[oy+3] = hblur(oy+2)
        hb3 = hblur(oy + 2);
        dst[oy * OW] = ((hb0 + hb3) + 3.0f * (hb1 + hb2)) * (1.0f / 64.0f);
        hb0 = hb1; hb1 = hb2; hb2 = hb3;
    }
    // oy = 62: padded row 65 reflects to src row 62
    hb3 = hblur(62);
    dst[(OH - 1) * OW] = ((hb0 + hb3) + 3.0f * (hb1 + hb2)) * (1.0f / 64.0f);
}

extern "C" void kernel_launch(void* const* d_in, const int* in_sizes, int n_in,
                              void* d_out, int out_size)
{
    const float* h = (const float*)d_in[0];
    float* out = (float*)d_out;

    const int n_img = 8 * 256;              // 2048 images of 64x512
    dim3 block(128);
    dim3 grid((OW + 127) / 128, n_img);     // 4 x 2048 blocks
    Blur_49976239456711_kernel<<<grid, block>>>(h, out);
}

// round 2
// speedup vs baseline: 1.0520x; 1.0520x over previous
#include <cuda_runtime.h>

// Depthwise separable 4x4 blur, filter [1,3,3,1] (x) [1,3,3,1] / 64.
// Input  (8, 256, 64, 512) fp32, W-pad circular(1), H-pad reflect(1).
// Output (8, 256, 63, 511) fp32.
//
// R2: float4 (LDG.128) loads. Thread t owns outputs 4t+1..4t+4 (thread 127's
// 4th output wraps to ox=0). Two aligned float4 loads per row cover the 7-col
// tap span; vertical pass uses a rolling window of 4 float4 accumulators.

#define W   512
#define H   64
#define OW  511
#define OH  63

__device__ __forceinline__ float4 f4_vblur(const float4& a, const float4& b,
                                           const float4& c, const float4& d)
{
    // ((a + d) + 3*(b + c)) / 64
    float4 r;
    r.x = ((a.x + d.x) + 3.0f * (b.x + c.x)) * (1.0f / 64.0f);
    r.y = ((a.y + d.y) + 3.0f * (b.y + c.y)) * (1.0f / 64.0f);
    r.z = ((a.z + d.z) + 3.0f * (b.z + c.z)) * (1.0f / 64.0f);
    r.w = ((a.w + d.w) + 3.0f * (b.w + c.w)) * (1.0f / 64.0f);
    return r;
}

__global__ __launch_bounds__(128) void Blur_49976239456711_kernel(
    const float* __restrict__ in, float* __restrict__ out)
{
    const int t   = threadIdx.x;           // 0..127, owns cols 4t..4t+3
    const int img = blockIdx.x;            // 0..2047

    const float* __restrict__ src = in  + (size_t)img * (H * W);
    float*       __restrict__ dst = out + (size_t)img * (OH * OW);

    const int cA = 4 * t;
    const int cB = (4 * t + 4) & (W - 1);  // wraps 512 -> 0 for t=127

    // Horizontal blur for outputs ox = 4t+1 .. 4t+4 at src row y.
    auto hblur4 = [&](int y) -> float4 {
        const float4 A = __ldg(reinterpret_cast<const float4*>(src + y * W + cA));
        const float4 B = __ldg(reinterpret_cast<const float4*>(src + y * W + cB));
        float4 r;
        r.x = (A.x + A.w) + 3.0f * (A.y + A.z);   // ox=4t+1: cols 4t..4t+3
        r.y = (A.y + B.x) + 3.0f * (A.z + A.w);   // ox=4t+2
        r.z = (A.z + B.y) + 3.0f * (A.w + B.x);   // ox=4t+3
        r.w = (A.w + B.z) + 3.0f * (B.x + B.y);   // ox=4t+4 (t=127: ox=0)
        return r;
    };

    const int ox0 = 4 * t + 1;
    const bool full = (t < 127);            // t=127: ox 509,510,(skip 511),0

    auto store4 = [&](int oy, const float4& v) {
        float* row = dst + oy * OW;
        row[ox0]     = v.x;
        row[ox0 + 1] = v.y;
        if (full) {
            row[ox0 + 2] = v.z;
            row[ox0 + 3] = v.w;
        } else {
            row[0] = v.w;
        }
    };

    // Reflect rows: padded py -> src row (py==0 -> 1, py==65 -> 62, else py-1).
    // Rolling window HB[py..py+3]; output oy consumes padded rows oy..oy+3.
    float4 hb0 = hblur4(1);   // HB[0] = src row 1
    float4 hb1 = hblur4(0);   // HB[1] = src row 0
    float4 hb2 = hb0;         // HB[2] = src row 1
    float4 hb3;

    #pragma unroll 4
    for (int oy = 0; oy < OH - 1; ++oy) {   // oy = 0..61: HB[oy+3] = src row oy+2
        hb3 = hblur4(oy + 2);
        store4(oy, f4_vblur(hb0, hb1, hb2, hb3));
        hb0 = hb1; hb1 = hb2; hb2 = hb3;
    }
    // oy = 62: padded row 65 reflects to src row 62
    hb3 = hblur4(62);
    store4(OH - 1, f4_vblur(hb0, hb1, hb2, hb3));
}

extern "C" void kernel_launch(void* const* d_in, const int* in_sizes, int n_in,
                              void* d_out, int out_size)
{
    const float* h = (const float*)d_in[0];
    float* out = (float*)d_out;

    const int n_img = 8 * 256;              // 2048 images of 64x512
    Blur_49976239456711_kernel<<<n_img, 128>>>(h, out);
}

// round 3
// speedup vs baseline: 1.2559x; 1.1939x over previous
#include <cuda_runtime.h>

// Depthwise separable 4x4 blur, filter [1,3,3,1] (x) [1,3,3,1] / 64.
// Input  (8, 256, 64, 512) fp32, W-pad circular(1), H-pad reflect(1).
// Output (8, 256, 63, 511) fp32.
//
// R3: explicit 4-deep register prefetch ring. Each thread keeps 8 LDG.128
// continuously in flight (rows oy+2..oy+5 while computing output oy), fixing
// the in-flight-bytes deficit that capped R1/R2 at ~4 TB/s.

#define W   512
#define H   64
#define OW  511
#define OH  63

__device__ __forceinline__ float4 f4_vblur(const float4& a, const float4& b,
                                           const float4& c, const float4& d)
{
    float4 r;
    r.x = ((a.x + d.x) + 3.0f * (b.x + c.x)) * (1.0f / 64.0f);
    r.y = ((a.y + d.y) + 3.0f * (b.y + c.y)) * (1.0f / 64.0f);
    r.z = ((a.z + d.z) + 3.0f * (b.z + c.z)) * (1.0f / 64.0f);
    r.w = ((a.w + d.w) + 3.0f * (b.w + c.w)) * (1.0f / 64.0f);
    return r;
}

__device__ __forceinline__ float4 f4_hblur(const float4& A, const float4& B)
{
    // outputs ox = 4t+1..4t+4 from src cols A=[4t..4t+3], B=[4t+4..4t+7]
    float4 r;
    r.x = (A.x + A.w) + 3.0f * (A.y + A.z);
    r.y = (A.y + B.x) + 3.0f * (A.z + A.w);
    r.z = (A.z + B.y) + 3.0f * (A.w + B.x);
    r.w = (A.w + B.z) + 3.0f * (B.x + B.y);
    return r;
}

__global__ __launch_bounds__(128) void Blur_49976239456711_kernel(
    const float* __restrict__ in, float* __restrict__ out)
{
    const int t   = threadIdx.x;           // 0..127, owns src cols 4t..4t+3
    const int img = blockIdx.x;            // 0..2047

    const float* __restrict__ src = in  + (size_t)img * (H * W);
    float*       __restrict__ dst = out + (size_t)img * (OH * OW);

    const int cA = 4 * t;
    const int cB = (4 * t + 4) & (W - 1);  // wraps 512 -> 0 for t=127

    const int ox0  = 4 * t + 1;
    const bool full = (t < 127);           // t=127 covers ox 509,510,(skip),0

    auto store4 = [&](int oy, const float4& v) {
        float* row = dst + oy * OW;
        row[ox0]     = v.x;
        row[ox0 + 1] = v.y;
        if (full) {
            row[ox0 + 2] = v.z;
            row[ox0 + 3] = v.w;
        } else {
            row[0] = v.w;
        }
    };

    // ── 4-deep prefetch ring: slot s holds src row (loaded 4 iters ahead) ──
    float4 pa[4], pb[4];

    auto issue = [&](int y, int s) {
        pa[s] = __ldg(reinterpret_cast<const float4*>(src + y * W + cA));
        pb[s] = __ldg(reinterpret_cast<const float4*>(src + y * W + cB));
    };

    // Prologue: prefetch rows 2..5 (consumed at oy = 0..3), plus rows 1,0
    // for the initial vertical window (reflect: padded 0->src 1, padded 1->src 0,
    // padded 2->src 1).
    issue(2, 0); issue(3, 1); issue(4, 2); issue(5, 3);

    const float4 A1 = __ldg(reinterpret_cast<const float4*>(src + 1 * W + cA));
    const float4 B1 = __ldg(reinterpret_cast<const float4*>(src + 1 * W + cB));
    const float4 A0 = __ldg(reinterpret_cast<const float4*>(src + 0 * W + cA));
    const float4 B0 = __ldg(reinterpret_cast<const float4*>(src + 0 * W + cB));

    float4 hb0 = f4_hblur(A1, B1);   // HB[padded 0] = src row 1
    float4 hb1 = f4_hblur(A0, B0);   // HB[padded 1] = src row 0
    float4 hb2 = hb0;                // HB[padded 2] = src row 1
    float4 hb3;

    // Main loop: output oy consumes src row oy+2 from slot (oy&3), then
    // refills that slot with src row oy+6 (kept 4 iterations in flight).
    #pragma unroll 4
    for (int oy = 0; oy < OH - 1; ++oy) {          // oy = 0..61
        const int s = oy & 3;
        hb3 = f4_hblur(pa[s], pb[s]);              // src row oy+2
        const int ny = oy + 6;
        if (ny < H) issue(ny, s);                  // refill (oy <= 57)
        store4(oy, f4_vblur(hb0, hb1, hb2, hb3));
        hb0 = hb1; hb1 = hb2; hb2 = hb3;
    }

    // oy = 62: padded row 65 reflects to src row 62 (hot in L1/L2 — just reload)
    {
        const float4 A = __ldg(reinterpret_cast<const float4*>(src + 62 * W + cA));
        const float4 B = __ldg(reinterpret_cast<const float4*>(src + 62 * W + cB));
        hb3 = f4_hblur(A, B);
        store4(OH - 1, f4_vblur(hb0, hb1, hb2, hb3));
    }
}

extern "C" void kernel_launch(void* const* d_in, const int* in_sizes, int n_in,
                              void* d_out, int out_size)
{
    const float* h = (const float*)d_in[0];
    float* out = (float*)d_out;

    const int n_img = 8 * 256;              // 2048 images of 64x512
    Blur_49976239456711_kernel<<<n_img, 128>>>(h, out);
}